// round 14
// baseline (speedup 1.0000x reference)
#include <cuda_runtime.h>
#include <math.h>
#include <stdint.h>

// ---------------------------------------------------------------------------
// 2-layer LSTM (T=1024, B=128, E=58, H=256) + Linear(256->33) + softplus.
//
// R14 vs R13: warp specialization. 288 threads = 8 compute warps + 1 service
// warp. The service warp owns all flag polls (acquire) and all A-staging
// (its own poll -> dependent LDG order makes the speculation safe), hidden
// under the compute warps' GEMM/epilogue phases. Barriers per slot: 4
// (was 7). Staging and poll latency fully off the critical path.
// ---------------------------------------------------------------------------

namespace {
constexpr int TT = 1024;
constexpr int BB = 128;
constexpr int EE = 58;
constexpr int HH = 256;
constexpr int OO = 33;

constexpr int HT = 16;             // hidden units per CTA
constexpr int BT = 16;             // batch per CTA
constexpr int HS = HH / HT;        // 16 hidden slices
constexpr int NCTA = 128;          // 16 x 8
constexpr int NTHR = 288;          // 8 compute warps + 1 service warp
constexpr int HP = HH / 2;         // 128 k-pairs
constexpr int PJ = 68;             // Part row stride (floats)
}

// Scratch (static __device__: allocation-free per harness rules)
__device__ float2 g_y0[(size_t)TT * HP * BB];   // [t][hpair][b]
__device__ float2 g_y1[(size_t)TT * HP * BB];
__device__ float  g_xp0[(size_t)TT * BB * HH * 4];  // [t][b][h][gate]
__device__ unsigned g_flags[2 * NCTA];

__global__ void reset_kernel() {
    int i = threadIdx.x;
    if (i < 2 * NCTA) g_flags[i] = 0u;
}

__device__ __forceinline__ void ffma2(uint64_t& d, uint64_t a, uint64_t b) {
    asm("fma.rn.f32x2 %0, %1, %2, %0;" : "+l"(d) : "l"(a), "l"(b));
}
__device__ __forceinline__ float fast_sigmoid(float x) {
    return __fdividef(1.f, 1.f + __expf(-x));
}
__device__ __forceinline__ float fast_tanh(float x) {
    float t = __expf(-2.f * fabsf(x));
    float r = __fdividef(1.f - t, 1.f + t);
    return copysignf(r, x);
}

// Service-warp poll: lanes < HS watch one flag each (acquire), whole warp
// spins until all watched flags reach target.
__device__ __forceinline__ void svc_poll(const unsigned* grp, unsigned target, int lane) {
    const bool watch = lane < HS;
    unsigned v = 0xffffffffu;
    do {
        if (watch)
            asm volatile("ld.acquire.gpu.global.u32 %0, [%1];" : "=r"(v) : "l"(grp + lane));
    } while (__any_sync(0xffffffffu, watch && (v < target)));
}

// ---------------------------------------------------------------------------
// xp0 precompute: xp0[t][b][h][g] = sum_e x[t][b][e]*W_ih0[g*H+h][e] + biases
// ---------------------------------------------------------------------------
__global__ void __launch_bounds__(256)
xp0_kernel(const float* __restrict__ x,       // [T][B][E]
           const float* __restrict__ W_ih0,   // [4H][E]
           const float* __restrict__ b_ih0,
           const float* __restrict__ b_hh0) {
    __shared__ float xs[64][EE];
    __shared__ float ws[4][32][EE];
    __shared__ float bs[4][32];
    const int t = blockIdx.x;
    const int hbase = blockIdx.y * 32;
    const int bbase = blockIdx.z * 64;
    const int tid = threadIdx.x;

    for (int i = tid; i < 64 * EE; i += 256) {
        int b = i / EE, e = i - b * EE;
        xs[b][e] = x[((size_t)t * BB + bbase + b) * EE + e];
    }
    for (int i = tid; i < 4 * 32 * EE; i += 256) {
        int e = i % EE; int r = i / EE; int g = r >> 5, hh = r & 31;
        ws[g][hh][e] = W_ih0[(size_t)(g * HH + hbase + hh) * EE + e];
    }
    if (tid < 128) {
        int g = tid >> 5, hh = tid & 31;
        bs[g][hh] = b_ih0[g * HH + hbase + hh] + b_hh0[g * HH + hbase + hh];
    }
    __syncthreads();

    const int bb = tid >> 3;
    const int hq = tid & 7;
    float acc[2][4][4] = {};
    for (int e = 0; e < EE; e++) {
        float x0 = xs[bb * 2][e], x1 = xs[bb * 2 + 1][e];
        #pragma unroll
        for (int h = 0; h < 4; h++)
            #pragma unroll
            for (int g = 0; g < 4; g++) {
                float w = ws[g][hq * 4 + h][e];
                acc[0][h][g] += x0 * w;
                acc[1][h][g] += x1 * w;
            }
    }
    #pragma unroll
    for (int bi = 0; bi < 2; bi++)
        #pragma unroll
        for (int h = 0; h < 4; h++) {
            float4 v;
            v.x = acc[bi][h][0] + bs[0][hq * 4 + h];
            v.y = acc[bi][h][1] + bs[1][hq * 4 + h];
            v.z = acc[bi][h][2] + bs[2][hq * 4 + h];
            v.w = acc[bi][h][3] + bs[3][hq * 4 + h];
            *(float4*)&g_xp0[(((size_t)t * BB + bbase + bb * 2 + bi) * HH
                              + hbase + hq * 4 + h) * 4] = v;
        }
}

// 32 k-pairs GEMM: 4 cols x 4 batches per thread (f32x2 even/odd-k partials).
__device__ __forceinline__ void gemm32(const float2* __restrict__ Wb,
                                       const float2* __restrict__ Ab,
                                       uint64_t acc[4][4]) {
    const char* wp = (const char*)Wb;
    const char* ip = (const char*)Ab;
    #pragma unroll 4
    for (int k = 0; k < 32; k++) {
        const ulonglong2 w01 = *(const ulonglong2*)(wp);
        const ulonglong2 w23 = *(const ulonglong2*)(wp + 16);
        const ulonglong2 i01 = *(const ulonglong2*)(ip);
        const ulonglong2 i23 = *(const ulonglong2*)(ip + 16);
        ffma2(acc[0][0], w01.x, i01.x); ffma2(acc[1][0], w01.y, i01.x);
        ffma2(acc[2][0], w23.x, i01.x); ffma2(acc[3][0], w23.y, i01.x);
        ffma2(acc[0][1], w01.x, i01.y); ffma2(acc[1][1], w01.y, i01.y);
        ffma2(acc[2][1], w23.x, i01.y); ffma2(acc[3][1], w23.y, i01.y);
        ffma2(acc[0][2], w01.x, i23.x); ffma2(acc[1][2], w01.y, i23.x);
        ffma2(acc[2][2], w23.x, i23.x); ffma2(acc[3][2], w23.y, i23.x);
        ffma2(acc[0][3], w01.x, i23.y); ffma2(acc[1][3], w01.y, i23.y);
        ffma2(acc[2][3], w23.x, i23.y); ffma2(acc[3][3], w23.y, i23.y);
        wp += 512;
        ip += 128;
    }
}

__global__ void __launch_bounds__(NTHR, 1)
lstm_fused_kernel(const float* __restrict__ W_hh0,  // (4H, H)
                  const float* __restrict__ W_ih1,  // (4H, H)
                  const float* __restrict__ W_hh1,  // (4H, H)
                  const float* __restrict__ b_ih1,
                  const float* __restrict__ b_hh1,
                  const float* __restrict__ h0,     // (2, B, H)
                  const float* __restrict__ c0,     // (2, B, H)
                  float* __restrict__ hn,           // (2, B, H)
                  float* __restrict__ cn)           // (2, B, H)
{
    extern __shared__ float2 smp[];
    float2* Wp0 = smp;                      // [128][64]  W_hh0 k-pairs
    float2* Wp1 = Wp0 + 128 * 64;           // [256][64]  W_ih1 | W_hh1 k-pairs
    float2* A   = Wp1 + 256 * 64;           // [128][16]  shared input buffer
    float*  P   = (float*)(A + 128 * 16);   // [4][16][PJ] partials

    const int tid   = threadIdx.x;
    const bool svc  = (tid >= 256);         // warp 8 = service warp
    const int lane  = tid & 31;
    const int cta   = blockIdx.x;
    const int hsl   = cta & (HS - 1);
    const int bsl   = cta >> 4;
    const int hbase = hsl * HT;
    const int bbase = bsl * BT;

    // ---- stage weight slices once ----
    for (int i = tid; i < 128 * 64; i += NTHR) {
        int jl = i >> 7;
        int kp = i & 127;
        int gate = jl >> 4, hh = jl & 15;
        int row = gate * HH + hbase + hh;
        Wp0[(size_t)kp * 64 + jl] = ((const float2*)(W_hh0 + (size_t)row * HH))[kp];
    }
    for (int i = tid; i < 256 * 64; i += NTHR) {
        int jl = i >> 8;
        int kp = i & 255;
        int gate = jl >> 4, hh = jl & 15;
        int row = gate * HH + hbase + hh;
        float2 w = (kp < 128)
            ? ((const float2*)(W_ih1 + (size_t)row * HH))[kp]
            : ((const float2*)(W_hh1 + (size_t)row * HH))[kp - 128];
        Wp1[(size_t)kp * 64 + jl] = w;
    }

    // ---- compute-warp GEMM mapping (warps 0..7) ----
    const int wrp = tid >> 5;
    const int kg  = wrp >> 1;
    const int bh  = wrp & 1;
    const int jt  = lane >> 1;
    const int bq  = lane & 1;
    const int b2  = bh * 8 + bq * 4;
    const size_t wOff = (size_t)(kg * 32) * 64 + jt * 4;
    const size_t aOff = (size_t)(kg * 32) * 16 + b2;

    // ---- epilogue mapping (tid < 256) ----
    const int eb = (tid >> 4) & 15;
    const int eh = tid & 15;
    const float bias1_0 = b_ih1[0 * HH + hbase + eh] + b_hh1[0 * HH + hbase + eh];
    const float bias1_1 = b_ih1[1 * HH + hbase + eh] + b_hh1[1 * HH + hbase + eh];
    const float bias1_2 = b_ih1[2 * HH + hbase + eh] + b_hh1[2 * HH + hbase + eh];
    const float bias1_3 = b_ih1[3 * HH + hbase + eh] + b_hh1[3 * HH + hbase + eh];
    float c0acc = c0[(bbase + eb) * HH + hbase + eh];
    float c1acc = c0[(size_t)BB * HH + (bbase + eb) * HH + hbase + eh];

    const unsigned* flg0_grp = &g_flags[bsl * HS];
    const unsigned* flg1_grp = &g_flags[NCTA + bsl * HS];
    unsigned* flg0_self = &g_flags[cta];
    unsigned* flg1_self = &g_flags[NCTA + cta];

    // ---- prologue: A := h0 (layer 0), first xp0 prefetch ----
    for (int i = tid; i < 128 * 16; i += NTHR) {
        int kp = i >> 4, b = i & 15;
        A[kp * 16 + b] = ((const float2*)h0)[(size_t)(bbase + b) * HP + kp];
    }
    uint4 xpv = *(const uint4*)&g_xp0[(((size_t)0 * BB + bbase + eb) * HH
                                       + hbase + eh) * 4];
    __syncthreads();

    for (int t = 0; t <= TT; t++) {
        uint64_t acc0[4][4] = {};
        uint64_t acc1[4][4] = {};

        // ================= phase B: GEMMs on A = y0(t-1) =================
        if (!svc) {
            if (t < TT) gemm32(Wp0 + wOff, A + aOff, acc0);   // L0 h-GEMM(t)
            if (t > 0)  gemm32(Wp1 + wOff, A + aOff, acc1);   // L1 x-GEMM(t-1)
            if (t < TT) {
                float* pb = P + kg * (16 * PJ) + b2 * PJ + jt * 4;
                #pragma unroll
                for (int bi = 0; bi < 4; bi++) {
                    union { uint64_t u; float2 f; } a0, a1, a2, a3;
                    a0.u = acc0[0][bi]; a1.u = acc0[1][bi];
                    a2.u = acc0[2][bi]; a3.u = acc0[3][bi];
                    float4 v;
                    v.x = a0.f.x + a0.f.y; v.y = a1.f.x + a1.f.y;
                    v.z = a2.f.x + a2.f.y; v.w = a3.f.x + a3.f.y;
                    *(float4*)(pb + bi * PJ) = v;
                }
            }
        } else {
            if (t >= 2) svc_poll(flg1_grp, (unsigned)(t - 1), lane);  // y1(t-2)
        }
        __syncthreads();   // SYNC_B

        // ====== phase C: epi0 (compute)  |  stage A := y1(t-2) (service) ======
        if (!svc) {
            if (t < TT) {
                float4 xf = *(float4*)&xpv;
                float s0 = xf.x, s1 = xf.y, s2 = xf.z, s3 = xf.w;
                #pragma unroll
                for (int p = 0; p < 4; p++) {
                    const float* pp = P + p * (16 * PJ) + eb * PJ;
                    s0 += pp[ 0 + eh];
                    s1 += pp[16 + eh];
                    s2 += pp[32 + eh];
                    s3 += pp[48 + eh];
                }
                const float ig = fast_sigmoid(s0);
                const float fg = fast_sigmoid(s1);
                const float gt = fast_tanh(s2);
                const float og = fast_sigmoid(s3);
                c0acc = fg * c0acc + ig * gt;
                const float hv = og * fast_tanh(c0acc);
                const float hv1 = __shfl_down_sync(0xffffffffu, hv, 1);
                if (!(eh & 1))
                    g_y0[(size_t)t * HP * BB + ((hbase + eh) >> 1) * BB + (bbase + eb)] =
                        make_float2(hv, hv1);
                if (t == TT - 1) {
                    hn[(bbase + eb) * HH + hbase + eh] = hv;
                    cn[(bbase + eb) * HH + hbase + eh] = c0acc;
                }
            }
            if (t + 1 < TT)   // prefetch xp0(t+1), consumed next slot
                xpv = *(const uint4*)&g_xp0[(((size_t)(t + 1) * BB + bbase + eb) * HH
                                             + hbase + eh) * 4];
        } else {
            if (t == 1) {
                const float2* h1i = (const float2*)(h0 + (size_t)BB * HH);
                for (int m = lane; m < 128 * 16; m += 32) {
                    int kp = m >> 4, b = m & 15;
                    A[kp * 16 + b] = h1i[(size_t)(bbase + b) * HP + kp];
                }
            } else if (t >= 2) {
                const float2* src = g_y1 + (size_t)(t - 2) * HP * BB;
                #pragma unroll 8
                for (int m = 0; m < 32; m++) {
                    int e = (m << 5) + lane;
                    int kp = e >> 3, bp = e & 7;
                    *(uint4*)&A[kp * 16 + bp * 2] =
                        *(const uint4*)&src[(size_t)kp * BB + bbase + bp * 2];
                }
            }
        }
        __syncthreads();   // SYNC_C
        if (tid == 0 && t < TT)
            asm volatile("st.release.gpu.global.u32 [%0], %1;"
                         :: "l"(flg0_self), "r"((unsigned)(t + 1)) : "memory");

        // ====== phase D: L1 h-GEMM (compute)  |  poll flg0(t+1) (service) ======
        if (!svc) {
            if (t > 0) {
                gemm32(Wp1 + (size_t)128 * 64 + wOff, A + aOff, acc1);
                float* pb = P + kg * (16 * PJ) + b2 * PJ + jt * 4;
                #pragma unroll
                for (int bi = 0; bi < 4; bi++) {
                    union { uint64_t u; float2 f; } a0, a1, a2, a3;
                    a0.u = acc1[0][bi]; a1.u = acc1[1][bi];
                    a2.u = acc1[2][bi]; a3.u = acc1[3][bi];
                    float4 v;
                    v.x = a0.f.x + a0.f.y; v.y = a1.f.x + a1.f.y;
                    v.z = a2.f.x + a2.f.y; v.w = a3.f.x + a3.f.y;
                    *(float4*)(pb + bi * PJ) = v;
                }
            }
        } else {
            if (t <= TT - 1) svc_poll(flg0_grp, (unsigned)(t + 1), lane);  // y0(t)
        }
        __syncthreads();   // SYNC_D

        // ====== phase E: epi1 (compute)  |  stage A := y0(t) (service) ======
        if (!svc) {
            if (t > 0) {
                float s0 = bias1_0, s1 = bias1_1, s2 = bias1_2, s3 = bias1_3;
                #pragma unroll
                for (int p = 0; p < 4; p++) {
                    const float* pp = P + p * (16 * PJ) + eb * PJ;
                    s0 += pp[ 0 + eh];
                    s1 += pp[16 + eh];
                    s2 += pp[32 + eh];
                    s3 += pp[48 + eh];
                }
                const float ig = fast_sigmoid(s0);
                const float fg = fast_sigmoid(s1);
                const float gt = fast_tanh(s2);
                const float og = fast_sigmoid(s3);
                c1acc = fg * c1acc + ig * gt;
                const float hv = og * fast_tanh(c1acc);
                const float hv1 = __shfl_down_sync(0xffffffffu, hv, 1);
                if (!(eh & 1))
                    g_y1[(size_t)(t - 1) * HP * BB + ((hbase + eh) >> 1) * BB + (bbase + eb)] =
                        make_float2(hv, hv1);
                if (t - 1 == TT - 1) {
                    hn[(size_t)BB * HH + (bbase + eb) * HH + hbase + eh] = hv;
                    cn[(size_t)BB * HH + (bbase + eb) * HH + hbase + eh] = c1acc;
                }
            }
        } else {
            if (t <= TT - 1) {
                const float2* src = g_y0 + (size_t)t * HP * BB;
                #pragma unroll 8
                for (int m = 0; m < 32; m++) {
                    int e = (m << 5) + lane;
                    int kp = e >> 3, bp = e & 7;
                    *(uint4*)&A[kp * 16 + bp * 2] =
                        *(const uint4*)&src[(size_t)kp * BB + bbase + bp * 2];
                }
            }
        }
        __syncthreads();   // SYNC_E
        if (tid == 0 && t > 0)
            asm volatile("st.release.gpu.global.u32 [%0], %1;"
                         :: "l"(flg1_self), "r"((unsigned)t) : "memory");
    }
}

// Final projection + softplus: out[t][b][o] = softplus(y1[t]·W_out^T + b_out)
__global__ void __launch_bounds__(128, 4)
proj_kernel(const float* __restrict__ W_out,  // (33, 256)
            const float* __restrict__ b_out,  // (33,)
            float* __restrict__ out)          // [T][B][33]
{
    __shared__ float Wsm[HH * OO];
    const int t = blockIdx.x;
    const int b = threadIdx.x;

    for (int i = b; i < HH * OO; i += 128) {
        int k = i / OO;
        int o = i - k * OO;
        Wsm[k * OO + o] = W_out[o * HH + k];
    }
    __syncthreads();

    const float2* y = g_y1 + (size_t)t * HP * BB;
    float acc[OO];
    #pragma unroll
    for (int o = 0; o < OO; o++) acc[o] = b_out[o];

    #pragma unroll 2
    for (int kp = 0; kp < HP; kp++) {
        const float2 v = y[kp * BB + b];
        const float* w0 = &Wsm[(2 * kp) * OO];
        const float* w1 = &Wsm[(2 * kp + 1) * OO];
        #pragma unroll
        for (int o = 0; o < OO; o++) acc[o] += v.x * w0[o] + v.y * w1[o];
    }

    float* op = out + (size_t)t * BB * OO + b * OO;
    #pragma unroll
    for (int o = 0; o < OO; o++) {
        const float x = acc[o];
        op[o] = fmaxf(x, 0.f) + log1pf(__expf(-fabsf(x)));
    }
}

extern "C" void kernel_launch(void* const* d_in, const int* in_sizes, int n_in,
                              void* d_out, int out_size) {
    const float* x     = (const float*)d_in[0];
    const float* h0    = (const float*)d_in[1];
    const float* c0    = (const float*)d_in[2];
    const float* W_ih0 = (const float*)d_in[3];
    const float* W_hh0 = (const float*)d_in[4];
    const float* b_ih0 = (const float*)d_in[5];
    const float* b_hh0 = (const float*)d_in[6];
    const float* W_ih1 = (const float*)d_in[7];
    const float* W_hh1 = (const float*)d_in[8];
    const float* b_ih1 = (const float*)d_in[9];
    const float* b_hh1 = (const float*)d_in[10];
    const float* W_out = (const float*)d_in[11];
    const float* b_out = (const float*)d_in[12];

    float* out = (float*)d_out;
    float* hn  = out + (size_t)TT * BB * OO;   // (2,B,H)
    float* cn  = hn + 2 * BB * HH;             // (2,B,H)

    // smem: Wp0 64K + Wp1 128K + A 16K + P 4*16*68*4 = 230,400 B
    const int smemF = 128 * 64 * 8 + 256 * 64 * 8 + 128 * 16 * 8 + 4 * 16 * PJ * 4;
    cudaFuncSetAttribute((const void*)lstm_fused_kernel,
                         cudaFuncAttributeMaxDynamicSharedMemorySize, smemF);

    reset_kernel<<<1, 256>>>();

    dim3 xg(TT, 8, 2);
    xp0_kernel<<<xg, 256>>>(x, W_ih0, b_ih0, b_hh0);

    lstm_fused_kernel<<<NCTA, NTHR, smemF>>>(
        W_hh0, W_ih1, W_hh1, b_ih1, b_hh1, h0, c0, hn, cn);

    proj_kernel<<<TT, 128>>>(W_out, b_out, out);
}